// round 2
// baseline (speedup 1.0000x reference)
#include <cuda_runtime.h>
#include <cuda_bf16.h>
#include <cstdint>

// ---------------- problem constants ----------------
#define BDIM   4096
#define IDIM   256
#define ODIM   256
#define GG     8
#define KBASIS (IDIM * GG * GG)      // 16384
#define KTOT   (KBASIS + 2 * IDIM)   // 16896
#define NTOT   (2 * ODIM)            // 512

// ---------------- scratch (device globals; no allocs allowed) ----------------
__device__ __align__(16) float g_A[(size_t)BDIM * KTOT];     // 277 MB: [b][k] tf32-rounded
__device__ __align__(16) float g_Wt[(size_t)KTOT * NTOT];    // 34.6 MB: [k][n] tf32-rounded
__device__ __align__(16) float g_bias[NTOT];

// ---------------- helpers ----------------
__device__ __forceinline__ float tf32r(float x) {
    unsigned r;
    asm("cvt.rna.tf32.f32 %0, %1;" : "=r"(r) : "f"(x));
    return __uint_as_float(r);
}

__device__ __forceinline__ void cp16(void* sm, const void* gm) {
    unsigned a = (unsigned)__cvta_generic_to_shared(sm);
    asm volatile("cp.async.cg.shared.global [%0], [%1], 16;\n" :: "r"(a), "l"(gm) : "memory");
}

__device__ __forceinline__ void mma_tf32(float* d, const float* a, const float* b) {
    asm volatile(
        "mma.sync.aligned.m16n8k8.row.col.f32.tf32.tf32.f32 "
        "{%0,%1,%2,%3},{%4,%5,%6,%7},{%8,%9},{%0,%1,%2,%3};"
        : "+f"(d[0]), "+f"(d[1]), "+f"(d[2]), "+f"(d[3])
        : "r"(__float_as_uint(a[0])), "r"(__float_as_uint(a[1])),
          "r"(__float_as_uint(a[2])), "r"(__float_as_uint(a[3])),
          "r"(__float_as_uint(b[0])), "r"(__float_as_uint(b[1])));
}

// ---------------- P1: basis rows of A (separable exps) ----------------
// grid (4096, 4), 256 threads; block handles 64 i's of one b-row.
__global__ void basis_kernel(const float* __restrict__ xre, const float* __restrict__ xim) {
    __shared__ float eu[64][8];
    __shared__ float ev[64][8];
    const int b  = blockIdx.x;
    const int i0 = blockIdx.y * 64;
    const int t  = threadIdx.x;

    if (t < 128) {
        const int il = t >> 1, comp = t & 1;
        const float x = (comp ? xim : xre)[b * IDIM + i0 + il];
        float* dst = comp ? ev[il] : eu[il];
#pragma unroll
        for (int u = 0; u < 8; u++) {
            float lu = -2.0f + (float)u * (4.0f / 7.0f);
            float d  = x - lu;
            dst[u] = __expf(-d * d);
        }
    }
    __syncthreads();

    const size_t base = (size_t)b * KTOT + (size_t)i0 * 64;
#pragma unroll
    for (int j = 0; j < 4; j++) {
        int e  = t * 16 + j * 4;           // [0, 4096)
        int il = e >> 6;
        int u  = (e >> 3) & 7;
        int v  = e & 7;                    // 0 or 4
        float eus = eu[il][u];
        float4 val;
        val.x = tf32r(eus * ev[il][v + 0]);
        val.y = tf32r(eus * ev[il][v + 1]);
        val.z = tf32r(eus * ev[il][v + 2]);
        val.w = tf32r(eus * ev[il][v + 3]);
        *(float4*)&g_A[base + e] = val;
    }
}

// ---------------- P1b: silu rows of A ----------------
__global__ void silu_kernel(const float* __restrict__ xre, const float* __restrict__ xim) {
    int idx = blockIdx.x * 256 + threadIdx.x;   // 4096*512
    int b = idx >> 9;
    int j = idx & 511;
    float x = (j < 256) ? xre[b * IDIM + j] : xim[b * IDIM + j - 256];
    float s = x / (1.0f + __expf(-x));
    g_A[(size_t)b * KTOT + KBASIS + j] = tf32r(s);
}

// ---------------- P2: transpose RBF weights into Wt[k][n] ----------------
// grid (256 i, 4 o-quarters), 256 threads.
__global__ void wt_kernel(const float* __restrict__ rw, const float* __restrict__ cw) {
    __shared__ float s[64][132];   // [uv][n_local 0..127] (+pad)
    const int i  = blockIdx.x;
    const int q  = blockIdx.y;
    const int o0 = q * 64;
    const int t  = threadIdx.x;

    // load: 2 arrays x 64 o x 16 float4 (coalesced), scatter into smem
#pragma unroll
    for (int it = 0; it < 8; it++) {
        int lin = it * 256 + t;             // [0, 2048)
        int arr = lin >> 10;                // 0 = real, 1 = complex
        int l2  = lin & 1023;
        int ol  = l2 >> 4;
        int f4  = l2 & 15;
        const float* src = arr ? cw : rw;
        float4 wv = *(const float4*)&src[((size_t)(i * ODIM + o0 + ol)) * 64 + f4 * 4];
        int n = 2 * ol + arr;
        s[f4 * 4 + 0][n] = tf32r(wv.x);
        s[f4 * 4 + 1][n] = tf32r(wv.y);
        s[f4 * 4 + 2][n] = tf32r(wv.z);
        s[f4 * 4 + 3][n] = tf32r(wv.w);
    }
    __syncthreads();

    // write: 64 uv-rows x 128 n floats, coalesced
#pragma unroll
    for (int it = 0; it < 8; it++) {
        int lin = it * 256 + t;
        int uv  = lin >> 5;
        int f4  = lin & 31;
        float4 v = *(float4*)&s[uv][f4 * 4];
        *(float4*)&g_Wt[(size_t)(i * 64 + uv) * NTOT + q * 128 + f4 * 4] = v;
    }
}

// ---------------- P2b: silu weight rows of Wt ----------------
__global__ void wtsilu_kernel(const float* __restrict__ swre, const float* __restrict__ swim) {
    int idx = blockIdx.x * 256 + threadIdx.x;   // 512*512
    int k = idx >> 9;        // [0, 512)
    int n = idx & 511;
    int o = n >> 1, c = n & 1, i = k & 255;
    float v;
    if (k < 256) v = c ? swim[i * ODIM + o] : swre[i * ODIM + o];
    else         v = c ? swre[i * ODIM + o] : -swim[i * ODIM + o];
    g_Wt[(size_t)(KBASIS + k) * NTOT + n] = tf32r(v);
}

// ---------------- P3: bias sums ----------------
__global__ void bias_kernel(const float* __restrict__ bre, const float* __restrict__ bim) {
    int n = blockIdx.x;
    int o = n >> 1;
    const float* src = (n & 1) ? bim : bre;
    int t = threadIdx.x;
    float v = src[t * ODIM + o];
#pragma unroll
    for (int off = 16; off; off >>= 1) v += __shfl_down_sync(0xffffffffu, v, off);
    __shared__ float red[8];
    if ((t & 31) == 0) red[t >> 5] = v;
    __syncthreads();
    if (t == 0) {
        float s = 0.0f;
#pragma unroll
        for (int w = 0; w < 8; w++) s += red[w];
        g_bias[n] = s;
    }
}

// ---------------- GEMM: tf32 mma.sync, 128x128 tile, KC=32, cp.async 2-stage ----------------
#define KC      32
#define ASTRIDE 36
#define BSTRIDE 136
#define ASZ     (128 * ASTRIDE)   // floats per A buffer
#define BSZ     (KC * BSTRIDE)    // floats per B buffer
#define SMEM_BYTES ((2 * (ASZ + BSZ)) * 4)

__global__ __launch_bounds__(256, 1) void gemm_kernel(float* __restrict__ out) {
    extern __shared__ float smem[];
    float* Abuf[2] = { smem, smem + ASZ };
    float* Bbuf[2] = { smem + 2 * ASZ, smem + 2 * ASZ + BSZ };

    const int tid  = threadIdx.x;
    const int lane = tid & 31;
    const int warp = tid >> 5;
    const int wm   = warp & 1;        // 2 warp-rows of 64
    const int wn   = warp >> 1;       // 4 warp-cols of 32
    const int gid  = lane >> 2;
    const int tg   = lane & 3;
    const int m0   = blockIdx.x * 128;
    const int n0   = blockIdx.y * 128;

    float acc[4][4][4];
#pragma unroll
    for (int a = 0; a < 4; a++)
#pragma unroll
        for (int b = 0; b < 4; b++)
#pragma unroll
            for (int c = 0; c < 4; c++) acc[a][b][c] = 0.0f;

    const int NST = KTOT / KC;   // 528

    // prologue: stage 0 -> buf 0
    {
        const int kt = 0, buf = 0;
        long k0 = (long)kt * KC;
#pragma unroll
        for (int j = 0; j < 4; j++) {
            int id = tid + 256 * j;
            int r = id >> 3, sg = id & 7;
            cp16(&Abuf[buf][r * ASTRIDE + sg * 4], &g_A[(size_t)(m0 + r) * KTOT + k0 + sg * 4]);
        }
#pragma unroll
        for (int j = 0; j < 4; j++) {
            int id = tid + 256 * j;
            int r = id >> 5, sg = id & 31;
            cp16(&Bbuf[buf][r * BSTRIDE + sg * 4], &g_Wt[(size_t)(k0 + r) * NTOT + n0 + sg * 4]);
        }
        asm volatile("cp.async.commit_group;" ::: "memory");
        asm volatile("cp.async.wait_group 0;" ::: "memory");
        __syncthreads();
    }

    for (int kt = 0; kt < NST; kt++) {
        const int buf = kt & 1;
        if (kt + 1 < NST) {
            long k0 = (long)(kt + 1) * KC;
            const int nb = buf ^ 1;
#pragma unroll
            for (int j = 0; j < 4; j++) {
                int id = tid + 256 * j;
                int r = id >> 3, sg = id & 7;
                cp16(&Abuf[nb][r * ASTRIDE + sg * 4], &g_A[(size_t)(m0 + r) * KTOT + k0 + sg * 4]);
            }
#pragma unroll
            for (int j = 0; j < 4; j++) {
                int id = tid + 256 * j;
                int r = id >> 5, sg = id & 31;
                cp16(&Bbuf[nb][r * BSTRIDE + sg * 4], &g_Wt[(size_t)(k0 + r) * NTOT + n0 + sg * 4]);
            }
            asm volatile("cp.async.commit_group;" ::: "memory");
        }

        // compute on current buffer
        const float* as = Abuf[buf];
        const float* bs = Bbuf[buf];
#pragma unroll
        for (int k8 = 0; k8 < KC; k8 += 8) {
            float afr[4][4];
            float bfr[4][2];
#pragma unroll
            for (int mt = 0; mt < 4; mt++) {
                int r0 = wm * 64 + mt * 16 + gid;
                afr[mt][0] = as[r0 * ASTRIDE + k8 + tg];
                afr[mt][1] = as[(r0 + 8) * ASTRIDE + k8 + tg];
                afr[mt][2] = as[r0 * ASTRIDE + k8 + tg + 4];
                afr[mt][3] = as[(r0 + 8) * ASTRIDE + k8 + tg + 4];
            }
#pragma unroll
            for (int nt = 0; nt < 4; nt++) {
                int n = wn * 32 + nt * 8 + gid;
                bfr[nt][0] = bs[(k8 + tg) * BSTRIDE + n];
                bfr[nt][1] = bs[(k8 + tg + 4) * BSTRIDE + n];
            }
#pragma unroll
            for (int mt = 0; mt < 4; mt++)
#pragma unroll
                for (int nt = 0; nt < 4; nt++)
                    mma_tf32(acc[mt][nt], afr[mt], bfr[nt]);
        }

        asm volatile("cp.async.wait_group 0;" ::: "memory");
        __syncthreads();
    }

    // epilogue: add bias, write float2 pairs (re, im adjacent)
#pragma unroll
    for (int mt = 0; mt < 4; mt++) {
#pragma unroll
        for (int nt = 0; nt < 4; nt++) {
            int row = m0 + wm * 64 + mt * 16 + gid;
            int col = n0 + wn * 32 + nt * 8 + tg * 2;
            float2 bb = *(const float2*)&g_bias[col];
            float2 v0 = make_float2(acc[mt][nt][0] + bb.x, acc[mt][nt][1] + bb.y);
            float2 v1 = make_float2(acc[mt][nt][2] + bb.x, acc[mt][nt][3] + bb.y);
            *(float2*)&out[(size_t)row * NTOT + col]       = v0;
            *(float2*)&out[(size_t)(row + 8) * NTOT + col] = v1;
        }
    }
}

// ---------------- launch ----------------
extern "C" void kernel_launch(void* const* d_in, const int* in_sizes, int n_in,
                              void* d_out, int out_size) {
    const float* xre  = (const float*)d_in[0];
    const float* xim  = (const float*)d_in[1];
    const float* rw   = (const float*)d_in[2];
    const float* cw   = (const float*)d_in[3];
    const float* swre = (const float*)d_in[4];
    const float* swim = (const float*)d_in[5];
    const float* bre  = (const float*)d_in[6];
    const float* bim  = (const float*)d_in[7];
    float* out = (float*)d_out;

    static bool attr_set = false;
    if (!attr_set) {
        cudaFuncSetAttribute(gemm_kernel, cudaFuncAttributeMaxDynamicSharedMemorySize, SMEM_BYTES);
        attr_set = true;
    }

    basis_kernel<<<dim3(4096, 4), 256>>>(xre, xim);
    silu_kernel<<<(BDIM * 512) / 256, 256>>>(xre, xim);
    wt_kernel<<<dim3(256, 4), 256>>>(rw, cw);
    wtsilu_kernel<<<(512 * 512) / 256, 256>>>(swre, swim);
    bias_kernel<<<NTOT, 256>>>(bre, bim);
    gemm_kernel<<<dim3(BDIM / 128, NTOT / 128), 256, SMEM_BYTES>>>(out);
}

// round 6
// speedup vs baseline: 2.7770x; 2.7770x over previous
#include <cuda_runtime.h>
#include <cuda_fp16.h>
#include <cstdint>

// ---------------- problem constants ----------------
#define BDIM   4096
#define IDIM   256
#define ODIM   256
#define KBASIS (IDIM * 64)           // 16384
#define KTOT   (KBASIS + 2 * IDIM)   // 16896
#define NTOT   (2 * ODIM)            // 512

// GEMM tiling
#define MTILE  128
#define NTILE  128
#define KC     64                    // halves per stage-row = 128 B
#define STAGES 4
#define NST    (KTOT / KC)           // 264

// ---------------- scratch (device globals; no allocs allowed) ----------------
__device__ __align__(16) __half g_A[(size_t)BDIM * KTOT];    // 138 MB: [b][k] fp16
__device__ __align__(16) __half g_Wt[(size_t)NTOT * KTOT];   // 17.3 MB: [n][k] fp16 (K-major)
__device__ float g_bias[NTOT];

// ---------------- helpers ----------------
__device__ __forceinline__ uint32_t smem_u32(const void* p) {
    uint32_t a;
    asm("{ .reg .u64 t; cvta.to.shared.u64 t, %1; cvt.u32.u64 %0, t; }" : "=r"(a) : "l"(p));
    return a;
}

__device__ __forceinline__ void cp16s(uint32_t sm, const void* gm) {
    asm volatile("cp.async.cg.shared.global [%0], [%1], 16;\n" :: "r"(sm), "l"(gm) : "memory");
}

__device__ __forceinline__ void ldsm4(uint32_t* r, uint32_t addr) {
    asm volatile("ldmatrix.sync.aligned.m8n8.x4.shared.b16 {%0,%1,%2,%3}, [%4];"
                 : "=r"(r[0]), "=r"(r[1]), "=r"(r[2]), "=r"(r[3]) : "r"(addr));
}

__device__ __forceinline__ void mma_f16(float* d, const uint32_t* a, uint32_t b0, uint32_t b1) {
    asm volatile(
        "mma.sync.aligned.m16n8k16.row.col.f32.f16.f16.f32 "
        "{%0,%1,%2,%3},{%4,%5,%6,%7},{%8,%9},{%0,%1,%2,%3};"
        : "+f"(d[0]), "+f"(d[1]), "+f"(d[2]), "+f"(d[3])
        : "r"(a[0]), "r"(a[1]), "r"(a[2]), "r"(a[3]), "r"(b0), "r"(b1));
}

// ---------------- P1: basis rows of A (separable exps) ----------------
// grid (4096, 4), 256 threads; block handles 64 i's of one b-row.
__global__ void basis_kernel(const float* __restrict__ xre, const float* __restrict__ xim) {
    __shared__ float eu[64][8];
    __shared__ float ev[64][8];
    const int b  = blockIdx.x;
    const int i0 = blockIdx.y * 64;
    const int t  = threadIdx.x;

    if (t < 128) {
        const int il = t >> 1, comp = t & 1;
        const float x = (comp ? xim : xre)[b * IDIM + i0 + il];
        float* dst = comp ? ev[il] : eu[il];
#pragma unroll
        for (int u = 0; u < 8; u++) {
            float lu = -2.0f + (float)u * (4.0f / 7.0f);
            float d  = x - lu;
            dst[u] = __expf(-d * d);
        }
    }
    __syncthreads();

    const size_t base = (size_t)b * KTOT + (size_t)i0 * 64;
#pragma unroll
    for (int j = 0; j < 4; j++) {
        int e  = t * 16 + j * 4;           // [0, 4096)
        int il = e >> 6;
        int u  = (e >> 3) & 7;
        int v  = e & 7;                    // 0 or 4
        float eus = eu[il][u];
        __half2 p0 = __floats2half2_rn(eus * ev[il][v + 0], eus * ev[il][v + 1]);
        __half2 p1 = __floats2half2_rn(eus * ev[il][v + 2], eus * ev[il][v + 3]);
        *(__half2*)&g_A[base + e]     = p0;
        *(__half2*)&g_A[base + e + 2] = p1;
    }
}

// ---------------- P1b: silu rows of A ----------------
__global__ void silu_kernel(const float* __restrict__ xre, const float* __restrict__ xim) {
    int idx = blockIdx.x * 256 + threadIdx.x;   // 4096*512
    int b = idx >> 9;
    int j = idx & 511;
    float x = (j < 256) ? xre[b * IDIM + j] : xim[b * IDIM + j - 256];
    float s = x / (1.0f + __expf(-x));
    g_A[(size_t)b * KTOT + KBASIS + j] = __float2half_rn(s);
}

// ---------------- P2: weights -> Wt[n][k] K-major fp16 ----------------
__global__ void wt_kernel(const float* __restrict__ rw, const float* __restrict__ cw) {
    int idx = blockIdx.x * 256 + threadIdx.x;   // 512*256*16
    int f4 = idx & 15;
    int i  = (idx >> 4) & 255;
    int n  = idx >> 12;               // 0..511
    int o = n >> 1, c = n & 1;
    const float* src = c ? cw : rw;
    float4 w = *(const float4*)&src[((size_t)(i * ODIM + o)) * 64 + f4 * 4];
    size_t dst = (size_t)n * KTOT + i * 64 + f4 * 4;
    *(__half2*)&g_Wt[dst]     = __floats2half2_rn(w.x, w.y);
    *(__half2*)&g_Wt[dst + 2] = __floats2half2_rn(w.z, w.w);
}

// ---------------- P2b: silu weight cols of Wt ----------------
__global__ void wtsilu_kernel(const float* __restrict__ swre, const float* __restrict__ swim) {
    int idx = blockIdx.x * 256 + threadIdx.x;   // 512*512
    int j = idx & 511;
    int n = idx >> 9;
    int o = n >> 1, c = n & 1;
    float v;
    if (j < 256) { int i = j;       v = c ? swim[i * ODIM + o] : swre[i * ODIM + o]; }
    else         { int i = j - 256; v = c ? swre[i * ODIM + o] : -swim[i * ODIM + o]; }
    g_Wt[(size_t)n * KTOT + KBASIS + j] = __float2half_rn(v);
}

// ---------------- P3: bias sums ----------------
__global__ void bias_kernel(const float* __restrict__ bre, const float* __restrict__ bim) {
    int n = blockIdx.x;
    int o = n >> 1;
    const float* src = (n & 1) ? bim : bre;
    int t = threadIdx.x;
    float v = src[t * ODIM + o];
#pragma unroll
    for (int off = 16; off; off >>= 1) v += __shfl_down_sync(0xffffffffu, v, off);
    __shared__ float red[8];
    if ((t & 31) == 0) red[t >> 5] = v;
    __syncthreads();
    if (t == 0) {
        float s = 0.0f;
#pragma unroll
        for (int w = 0; w < 8; w++) s += red[w];
        g_bias[n] = s;
    }
}

// ---------------- GEMM: fp16 mma.m16n8k16, 128x128 tile, KC=64, 4-stage cp.async ----------------
#define STAGE_A     (MTILE * 128)           // 16384 B (128 rows x 128 B)
#define STAGE_BYTES (2 * STAGE_A)           // 32768 B (A + B)
#define SMEM_BYTES  (STAGES * STAGE_BYTES)  // 131072 B

__device__ __forceinline__ void load_stage(uint32_t sbase, int m0, int n0, int kt, int buf, int tid) {
    uint32_t sa = sbase + buf * STAGE_BYTES;
    uint32_t sbb = sa + STAGE_A;
    const __half* Ap = g_A  + (size_t)m0 * KTOT + (size_t)kt * KC;
    const __half* Bp = g_Wt + (size_t)n0 * KTOT + (size_t)kt * KC;
#pragma unroll
    for (int j = 0; j < 4; j++) {
        int id = tid + 256 * j;                // 1024 chunks of 16B
        int r = id >> 3, c = id & 7;
        uint32_t off = (uint32_t)(r * 128 + ((c ^ (r & 7)) * 16));
        cp16s(sa + off, Ap + (size_t)r * KTOT + c * 8);
    }
#pragma unroll
    for (int j = 0; j < 4; j++) {
        int id = tid + 256 * j;
        int r = id >> 3, c = id & 7;
        uint32_t off = (uint32_t)(r * 128 + ((c ^ (r & 7)) * 16));
        cp16s(sbb + off, Bp + (size_t)r * KTOT + c * 8);
    }
    asm volatile("cp.async.commit_group;" ::: "memory");
}

__global__ __launch_bounds__(256, 1) void gemm_kernel(float* __restrict__ out) {
    extern __shared__ char smem_raw[];
    const uint32_t sb = smem_u32(smem_raw);

    const int tid  = threadIdx.x;
    const int lane = tid & 31;
    const int warp = tid >> 5;
    const int wm   = warp & 1;        // 2 warp-rows of 64
    const int wn   = warp >> 1;       // 4 warp-cols of 32
    const int lr   = lane & 15;       // ldmatrix row within 16
    const int lh   = lane >> 4;       // ldmatrix 16B-chunk select
    const int m0   = blockIdx.x * MTILE;
    const int n0   = blockIdx.y * NTILE;

    float acc[4][4][4];
#pragma unroll
    for (int a = 0; a < 4; a++)
#pragma unroll
        for (int b = 0; b < 4; b++)
#pragma unroll
            for (int c = 0; c < 4; c++) acc[a][b][c] = 0.0f;

    // prologue: stages 0..2
    load_stage(sb, m0, n0, 0, 0, tid);
    load_stage(sb, m0, n0, 1, 1, tid);
    load_stage(sb, m0, n0, 2, 2, tid);

    for (int kt = 0; kt < NST; kt++) {
        if (kt < NST - 2)       asm volatile("cp.async.wait_group 2;" ::: "memory");
        else if (kt == NST - 2) asm volatile("cp.async.wait_group 1;" ::: "memory");
        else                    asm volatile("cp.async.wait_group 0;" ::: "memory");
        __syncthreads();

        // refill stage kt+3 (its buffer was consumed at iteration kt-1)
        if (kt + 3 < NST) load_stage(sb, m0, n0, kt + 3, (kt + 3) & (STAGES - 1), tid);

        const int buf = kt & (STAGES - 1);
        const uint32_t sa  = sb + buf * STAGE_BYTES;
        const uint32_t sbb = sa + STAGE_A;

#pragma unroll
        for (int ks = 0; ks < 4; ks++) {
            const uint32_t chunk = (uint32_t)(((ks * 2 + lh) ^ (lr & 7)) * 16);
            uint32_t afr[4][4];
#pragma unroll
            for (int mt = 0; mt < 4; mt++) {
                int row = wm * 64 + mt * 16 + lr;
                ldsm4(afr[mt], sa + (uint32_t)row * 128 + chunk);
            }
            uint32_t bfr[2][4];
#pragma unroll
            for (int nb = 0; nb < 2; nb++) {
                int row = wn * 32 + nb * 16 + lr;
                ldsm4(bfr[nb], sbb + (uint32_t)row * 128 + chunk);
            }
#pragma unroll
            for (int mt = 0; mt < 4; mt++)
#pragma unroll
                for (int nt = 0; nt < 4; nt++) {
                    int nb = nt >> 1, hi = nt & 1;
                    mma_f16(acc[mt][nt], afr[mt], bfr[nb][hi], bfr[nb][2 + hi]);
                }
        }
    }

    // epilogue: add bias, write float2 pairs (re, im adjacent)
    const int gid = lane >> 2;
    const int tg  = lane & 3;
#pragma unroll
    for (int mt = 0; mt < 4; mt++) {
#pragma unroll
        for (int nt = 0; nt < 4; nt++) {
            int row = m0 + wm * 64 + mt * 16 + gid;
            int col = n0 + wn * 32 + nt * 8 + tg * 2;
            float2 bb = *(const float2*)&g_bias[col];
            float2 v0 = make_float2(acc[mt][nt][0] + bb.x, acc[mt][nt][1] + bb.y);
            float2 v1 = make_float2(acc[mt][nt][2] + bb.x, acc[mt][nt][3] + bb.y);
            *(float2*)&out[(size_t)row * NTOT + col]       = v0;
            *(float2*)&out[(size_t)(row + 8) * NTOT + col] = v1;
        }
    }
}

// ---------------- launch ----------------
extern "C" void kernel_launch(void* const* d_in, const int* in_sizes, int n_in,
                              void* d_out, int out_size) {
    const float* xre  = (const float*)d_in[0];
    const float* xim  = (const float*)d_in[1];
    const float* rw   = (const float*)d_in[2];
    const float* cw   = (const float*)d_in[3];
    const float* swre = (const float*)d_in[4];
    const float* swim = (const float*)d_in[5];
    const float* bre  = (const float*)d_in[6];
    const float* bim  = (const float*)d_in[7];
    float* out = (float*)d_out;

    static bool attr_set = false;
    if (!attr_set) {
        cudaFuncSetAttribute(gemm_kernel, cudaFuncAttributeMaxDynamicSharedMemorySize, SMEM_BYTES);
        attr_set = true;
    }

    basis_kernel<<<dim3(4096, 4), 256>>>(xre, xim);
    silu_kernel<<<(BDIM * 512) / 256, 256>>>(xre, xim);
    wt_kernel<<<(NTOT * IDIM * 16) / 256, 256>>>(rw, cw);
    wtsilu_kernel<<<(NTOT * 512) / 256, 256>>>(swre, swim);
    bias_kernel<<<NTOT, 256>>>(bre, bim);
    gemm_kernel<<<dim3(BDIM / MTILE, NTOT / NTILE), 256, SMEM_BYTES>>>(out);
}